// round 11
// baseline (speedup 1.0000x reference)
#include <cuda_runtime.h>
#include <cuda_fp16.h>
#include <math.h>

// ---------------------------------------------------------------------------
// GeoMoE: sigmoid-gated top-3 MoE (E=23) + shared expert.
// fp16 tensor-core grouped GEMMs (mma.sync m16n8k16, fp32 accum).
// BM=128, BN=256, BK=32, warp tile 64x64, 4-stage cp.async (dynamic smem).
// ---------------------------------------------------------------------------

#define TOK   3136
#define DDIM  1024
#define HDIM  768
#define NE    23
#define TOPK  3

#define BM 128
#define BN 256
#define BK 32
#define MT 97
#define MAXR (MT * BM)
#define TS_TILES ((TOK + BM - 1) / BM)   // 25 shared-expert tiles

#define AS_STRIDE (BK + 8)    // 40 halfs = 80 B
#define BS_STRIDE (BN + 8)    // 264 halfs = 528 B
#define NSTAGE 4
#define DSM_BYTES (NSTAGE * (BM * AS_STRIDE + BK * BS_STRIDE) * 2)  // 108544

// ---------------- scratch (device globals; no allocation) ------------------
__device__ int   g_counts[NE];
__device__ float g_P[NE];
__device__ int   g_off[NE + 1];
__device__ int   g_topk_e[TOK * TOPK];
__device__ int   g_topk_rank[TOK * TOPK];
__device__ float g_topk_w[TOK * TOPK];
__device__ int   g_tok_of_row[MAXR];
__device__ float g_w_of_row[MAXR];
__device__ int   g_rows_of_tok[TOK * TOPK];

__device__ __align__(16) __half g_zero[DDIM];          // stays zero
__device__ __align__(16) __half g_xb  [TOK * DDIM];
__device__ __align__(16) __half g_w1b [NE * DDIM * HDIM];
__device__ __align__(16) __half g_w2b [NE * HDIM * DDIM];
__device__ __align__(16) __half g_ws1b[DDIM * HDIM];
__device__ __align__(16) __half g_ws2b[HDIM * DDIM];
__device__ __align__(16) __half g_Hb  [MAXR * HDIM];
__device__ __align__(16) __half g_Hsb [TOK * HDIM];
__device__ __align__(16) float  g_EO  [MAXR * DDIM];

__device__ __forceinline__ float gelu_exact(float v) {
    return 0.5f * v * (1.0f + erff(v * 0.70710678118654752f));
}

// ---------------------- fused fp32 -> fp16 (weights only) -------------------
#define NC_W1  (NE * DDIM * HDIM / 8)
#define NC_W2  (NE * HDIM * DDIM / 8)
#define NC_WS1 (DDIM * HDIM / 8)
#define NC_WS2 (HDIM * DDIM / 8)
#define NC_TOT (NC_W1 + NC_W2 + NC_WS1 + NC_WS2)

__device__ __forceinline__ void conv8(const float* __restrict__ s,
                                      __half* __restrict__ d, int i) {
    float4 a = reinterpret_cast<const float4*>(s)[2 * i + 0];
    float4 b = reinterpret_cast<const float4*>(s)[2 * i + 1];
    __half2 h0 = __floats2half2_rn(a.x, a.y);
    __half2 h1 = __floats2half2_rn(a.z, a.w);
    __half2 h2 = __floats2half2_rn(b.x, b.y);
    __half2 h3 = __floats2half2_rn(b.z, b.w);
    uint4 o;
    o.x = *reinterpret_cast<unsigned*>(&h0);
    o.y = *reinterpret_cast<unsigned*>(&h1);
    o.z = *reinterpret_cast<unsigned*>(&h2);
    o.w = *reinterpret_cast<unsigned*>(&h3);
    reinterpret_cast<uint4*>(d)[i] = o;
}

__global__ void convert_w_kernel(const float* __restrict__ w1,
                                 const float* __restrict__ w2,
                                 const float* __restrict__ ws1,
                                 const float* __restrict__ ws2) {
    int i = blockIdx.x * blockDim.x + threadIdx.x;
    if (i >= NC_TOT) return;
    if (i < NC_W1) { conv8(w1, g_w1b, i); return; }
    i -= NC_W1;
    if (i < NC_W2) { conv8(w2, g_w2b, i); return; }
    i -= NC_W2;
    if (i < NC_WS1) { conv8(ws1, g_ws1b, i); return; }
    i -= NC_WS1;
    conv8(ws2, g_ws2b, i);
}

// ---------------------------- init ------------------------------------------
__global__ void init_kernel() {
    int i = blockIdx.x * blockDim.x + threadIdx.x;
    if (i < MAXR) { g_tok_of_row[i] = -1; g_w_of_row[i] = 0.0f; }
    if (i < NE)   { g_counts[i] = 0; g_P[i] = 0.0f; }
}

// ---------------------- gating (+ x fp32->fp16 fused) -----------------------
__global__ __launch_bounds__(128) void gate_kernel(
    const float* __restrict__ x, const float* __restrict__ gw,
    const float* __restrict__ gb)
{
    __shared__ float s_x[DDIM];
    __shared__ float s_red[4][NE];
    __shared__ float s_gw[NE];

    const int t = blockIdx.x, tid = threadIdx.x, wid = tid >> 5;
    const float* xr = x + (size_t)t * DDIM;
    for (int i = tid; i < DDIM; i += 128) s_x[i] = xr[i];
    __syncthreads();

    {
        __half2* xo = reinterpret_cast<__half2*>(g_xb + (size_t)t * DDIM);
        #pragma unroll
        for (int j = 0; j < 4; j++) {
            int i2 = tid + j * 128;
            xo[i2] = __floats2half2_rn(s_x[2 * i2], s_x[2 * i2 + 1]);
        }
    }

    float acc[NE];
    #pragma unroll
    for (int e = 0; e < NE; e++) acc[e] = 0.0f;
    for (int k = tid; k < DDIM; k += 128) {
        float xv = s_x[k];
        const float* gr = gw + (size_t)k * NE;
        #pragma unroll
        for (int e = 0; e < NE; e++) acc[e] += xv * gr[e];
    }
    #pragma unroll
    for (int e = 0; e < NE; e++) {
        #pragma unroll
        for (int o = 16; o > 0; o >>= 1)
            acc[e] += __shfl_xor_sync(0xffffffffu, acc[e], o);
    }
    if ((tid & 31) == 0) {
        #pragma unroll
        for (int e = 0; e < NE; e++) s_red[wid][e] = acc[e];
    }
    __syncthreads();

    if (tid < NE) {
        float z = s_red[0][tid] + s_red[1][tid] + s_red[2][tid] + s_red[3][tid]
                  + gb[tid];
        s_gw[tid] = 1.0f / (1.0f + expf(-z));
    }
    __syncthreads();

    if (tid < NE) {
        float sum = 0.0f;
        #pragma unroll
        for (int e = 0; e < NE; e++) sum += s_gw[e];
        atomicAdd(&g_P[tid], s_gw[tid] / sum);
    }

    if (tid == 0) {
        float v0 = -1.f, v1 = -1.f, v2 = -1.f;
        int   i0 = 0,    i1 = 0,    i2 = 0;
        #pragma unroll
        for (int e = 0; e < NE; e++) {
            float v = s_gw[e];
            if (v > v0)      { v2=v1; i2=i1; v1=v0; i1=i0; v0=v; i0=e; }
            else if (v > v1) { v2=v1; i2=i1; v1=v;  i1=e; }
            else if (v > v2) { v2=v;  i2=e; }
        }
        float s3 = v0 + v1 + v2;
        int   ids[TOPK] = { i0, i1, i2 };
        float vs [TOPK] = { v0, v1, v2 };
        #pragma unroll
        for (int k = 0; k < TOPK; k++) {
            int rank = atomicAdd(&g_counts[ids[k]], 1);
            int idx  = t * TOPK + k;
            g_topk_e[idx]    = ids[k];
            g_topk_rank[idx] = rank;
            g_topk_w[idx]    = vs[k] / s3;
        }
    }
}

// -------------------- offsets (padded) + aux loss ----------------------------
__global__ void offsets_aux_kernel(float* __restrict__ out, int out_size) {
    if (threadIdx.x == 0) {
        int acc = 0;
        g_off[0] = 0;
        float aux = 0.0f;
        #pragma unroll
        for (int e = 0; e < NE; e++) {
            int c = g_counts[e];
            acc += ((c + BM - 1) / BM) * BM;
            g_off[e + 1] = acc;
            float P = g_P[e] / (float)TOK;
            float F = (float)NE * (float)c / (float)(TOPK * TOK);
            aux += P * F;
        }
        if (out_size > TOK * DDIM) out[TOK * DDIM] = aux;
    }
}

// ------------------------------ scatter --------------------------------------
__global__ void scatter_kernel() {
    int idx = blockIdx.x * blockDim.x + threadIdx.x;
    if (idx >= TOK * TOPK) return;
    int e   = g_topk_e[idx];
    int row = g_off[e] + g_topk_rank[idx];
    g_tok_of_row[row] = idx / TOPK;
    g_w_of_row[row]   = g_topk_w[idx];
    g_rows_of_tok[idx] = row;
}

// ------------------------------ fp16 GEMM ------------------------------------
// MODE 0 (merged L1):
//   bx <  MT: Hb  = gelu(gather(xb) @ w1b[e] + b1[e])    KD=1024 ND=768
//   bx >= MT: Hsb = gelu(xb @ ws1b + bs1)
// MODE 1: EO  = (Hb @ w2b[e] + b2[e]) * w_of_row         KD=768  ND=1024
// MODE 3: out = Hsb @ ws2b + bs2 + sum_k EO[rows_of_tok] KD=768  ND=1024

#define CP_ASYNC16(dst, src) \
    asm volatile("cp.async.cg.shared.global [%0], [%1], 16;\n" \
                 :: "r"(dst), "l"(src))
#define CP_COMMIT() asm volatile("cp.async.commit_group;\n")
#define CP_WAIT2()  asm volatile("cp.async.wait_group 2;\n")
#define CP_WAIT1()  asm volatile("cp.async.wait_group 1;\n")
#define CP_WAIT0()  asm volatile("cp.async.wait_group 0;\n")

#define LDMX4(r0,r1,r2,r3,addr) \
    asm volatile("ldmatrix.sync.aligned.m8n8.x4.shared.b16 {%0,%1,%2,%3}, [%4];\n" \
        : "=r"(r0),"=r"(r1),"=r"(r2),"=r"(r3) : "r"(addr))
#define LDMX4T(r0,r1,r2,r3,addr) \
    asm volatile("ldmatrix.sync.aligned.m8n8.x4.trans.shared.b16 {%0,%1,%2,%3}, [%4];\n" \
        : "=r"(r0),"=r"(r1),"=r"(r2),"=r"(r3) : "r"(addr))
#define MMA16816(c0,c1,c2,c3,a0,a1,a2,a3,b0,b1) \
    asm volatile("mma.sync.aligned.m16n8k16.row.col.f32.f16.f16.f32 " \
        "{%0,%1,%2,%3}, {%4,%5,%6,%7}, {%8,%9}, {%0,%1,%2,%3};\n" \
        : "+f"(c0),"+f"(c1),"+f"(c2),"+f"(c3) \
        : "r"(a0),"r"(a1),"r"(a2),"r"(a3), "r"(b0),"r"(b1))

template<int MODE, int KD, int ND>
__global__ __launch_bounds__(256) void hgemm_kernel(
    const __half* __restrict__ A,
    const __half* __restrict__ W,
    const float*  __restrict__ bias,
    const __half* __restrict__ Ws,     // MODE 0 shared-branch weights
    const float*  __restrict__ bs,     // MODE 0 shared-branch bias
    __half* __restrict__ OutH,         // MODE 0 expert out (Hb)
    __half* __restrict__ OutHs,        // MODE 0 shared out (Hsb)
    float*  __restrict__ OutF)
{
    extern __shared__ __half dsm[];
    const int n0 = blockIdx.y * BN;

    bool shared_part = (MODE == 0) && ((int)blockIdx.x >= MT);
    int m0;
    const __half* Wp;
    const float*  bp;
    if (MODE == 0 && shared_part) {
        m0 = ((int)blockIdx.x - MT) * BM;
        Wp = Ws; bp = bs;
    } else if (MODE == 0 || MODE == 1) {
        m0 = blockIdx.x * BM;
        if (m0 >= g_off[NE]) return;
        int e = 0;
        while (m0 >= g_off[e + 1]) e++;
        Wp = W + (size_t)e * KD * ND;
        bp = bias + (size_t)e * ND;
    } else {
        m0 = blockIdx.x * BM;
        Wp = W; bp = bias;
    }

    const int tid  = threadIdx.x;
    const int lane = tid & 31;
    const int wid  = tid >> 5;
    const int wm   = (wid >> 2) * 64;  // 2 warps along M (tile 64)
    const int wn   = (wid & 3) * 64;   // 4 warps along N (tile 64)

    // A loader: thread covers rows (ar, ar+64), 16B chunk at half-col ac
    const int ar = tid >> 2;
    const int ac = (tid & 3) * 8;
    const __half* aptr0;
    const __half* aptr1;
    {
        int r0 = m0 + ar, r1 = m0 + ar + 64;
        if (MODE == 0 && !shared_part) {
            int t0 = g_tok_of_row[r0], t1 = g_tok_of_row[r1];
            aptr0 = (t0 >= 0) ? A + (size_t)t0 * KD : g_zero;
            aptr1 = (t1 >= 0) ? A + (size_t)t1 * KD : g_zero;
        } else if (MODE == 1) {
            aptr0 = A + (size_t)r0 * KD;
            aptr1 = A + (size_t)r1 * KD;
        } else {
            aptr0 = (r0 < TOK) ? A + (size_t)r0 * KD : g_zero;
            aptr1 = (r1 < TOK) ? A + (size_t)r1 * KD : g_zero;
        }
        aptr0 += ac; aptr1 += ac;
    }
    // B loader: thread covers rows br+8p (p=0..3), 16B chunk at half-col bc
    const int br = tid >> 5;           // 0..7
    const int bc = (tid & 31) * 8;     // 0..248
    const __half* bptrB = Wp + (size_t)br * ND + n0 + bc;

    const unsigned as_base = (unsigned)__cvta_generic_to_shared(&dsm[0]);
    const unsigned bs_base = as_base + (unsigned)(NSTAGE * BM * AS_STRIDE) * 2;
    const unsigned aDst0 = as_base + (unsigned)(ar * AS_STRIDE + ac) * 2;
    const unsigned aDst1 = as_base + (unsigned)((ar + 64) * AS_STRIDE + ac) * 2;
    const unsigned bDstB = bs_base + (unsigned)(br * BS_STRIDE + bc) * 2;
    const unsigned aBufSz = (unsigned)(BM * AS_STRIDE) * 2;
    const unsigned bBufSz = (unsigned)(BK * BS_STRIDE) * 2;

    float acc[4][8][4];
    #pragma unroll
    for (int i = 0; i < 4; i++)
        #pragma unroll
        for (int j = 0; j < 8; j++)
            #pragma unroll
            for (int k = 0; k < 4; k++) acc[i][j][k] = 0.0f;

    const int NK = KD / BK;

    // prologue: stages 0..2 (3 groups in flight, 4 buffers)
    #pragma unroll
    for (int s = 0; s < 3; s++) {
        unsigned ab = s * aBufSz, bb = s * bBufSz;
        int k0 = s * BK;
        CP_ASYNC16(aDst0 + ab, aptr0 + k0);
        CP_ASYNC16(aDst1 + ab, aptr1 + k0);
        #pragma unroll
        for (int p = 0; p < 4; p++)
            CP_ASYNC16(bDstB + bb + (unsigned)(p * 8 * BS_STRIDE) * 2,
                       bptrB + (size_t)(k0 + p * 8) * ND);
        CP_COMMIT();
    }

    // ldmatrix source addresses (per warp lane)
    const unsigned aLdm = as_base +
        (unsigned)((wm + (lane & 15)) * AS_STRIDE + (lane >> 4) * 8) * 2;
    const unsigned bLdm = bs_base +
        (unsigned)((lane & 15) * BS_STRIDE + wn + (lane >> 4) * 8) * 2;

    for (int ks = 0; ks < NK; ks++) {
        const int rem = NK - 1 - ks;
        if (rem >= 2)      { CP_WAIT2(); }
        else if (rem == 1) { CP_WAIT1(); }
        else               { CP_WAIT0(); }
        __syncthreads();

        if (ks + 3 < NK) {
            int sb = (ks + 3) % NSTAGE;
            unsigned ab = sb * aBufSz, bb = sb * bBufSz;
            int k0 = (ks + 3) * BK;
            CP_ASYNC16(aDst0 + ab, aptr0 + k0);
            CP_ASYNC16(aDst1 + ab, aptr1 + k0);
            #pragma unroll
            for (int p = 0; p < 4; p++)
                CP_ASYNC16(bDstB + bb + (unsigned)(p * 8 * BS_STRIDE) * 2,
                           bptrB + (size_t)(k0 + p * 8) * ND);
            CP_COMMIT();
        }

        const int buf = ks % NSTAGE;
        const unsigned abuf = buf * aBufSz;
        const unsigned bbuf = buf * bBufSz;

        #pragma unroll
        for (int kst = 0; kst < 2; kst++) {
            unsigned aF[4][4], bF[4][4];
            #pragma unroll
            for (int mt = 0; mt < 4; mt++) {
                unsigned addr = aLdm + abuf +
                    (unsigned)(mt * 16 * AS_STRIDE + kst * 16) * 2;
                LDMX4(aF[mt][0], aF[mt][1], aF[mt][2], aF[mt][3], addr);
            }
            #pragma unroll
            for (int nt = 0; nt < 4; nt++) {
                unsigned addr = bLdm + bbuf +
                    (unsigned)(kst * 16 * BS_STRIDE + nt * 16) * 2;
                LDMX4T(bF[nt][0], bF[nt][1], bF[nt][2], bF[nt][3], addr);
            }
            #pragma unroll
            for (int mt = 0; mt < 4; mt++)
                #pragma unroll
                for (int n8 = 0; n8 < 8; n8++) {
                    unsigned b0 = bF[n8 >> 1][(n8 & 1) * 2];
                    unsigned b1 = bF[n8 >> 1][(n8 & 1) * 2 + 1];
                    MMA16816(acc[mt][n8][0], acc[mt][n8][1],
                             acc[mt][n8][2], acc[mt][n8][3],
                             aF[mt][0], aF[mt][1], aF[mt][2], aF[mt][3],
                             b0, b1);
                }
        }
    }

    // ------------------------------ epilogue --------------------------------
    const int gID = lane >> 2;
    const int tig = lane & 3;
    #pragma unroll
    for (int mt = 0; mt < 4; mt++) {
        #pragma unroll
        for (int n8 = 0; n8 < 8; n8++) {
            const int col = n0 + wn + n8 * 8 + tig * 2;
            const float2 bb = *reinterpret_cast<const float2*>(bp + col);
            const int r0 = m0 + wm + mt * 16 + gID;
            const int r1 = r0 + 8;
            float v00 = acc[mt][n8][0] + bb.x;
            float v01 = acc[mt][n8][1] + bb.y;
            float v10 = acc[mt][n8][2] + bb.x;
            float v11 = acc[mt][n8][3] + bb.y;

            if (MODE == 0) {
                __half* dst = shared_part ? OutHs : OutH;
                bool ok0 = shared_part ? (r0 < TOK) : true;
                bool ok1 = shared_part ? (r1 < TOK) : true;
                if (ok0) {
                    __half2 h = __floats2half2_rn(gelu_exact(v00),
                                                  gelu_exact(v01));
                    *reinterpret_cast<__half2*>(dst + (size_t)r0 * ND + col) = h;
                }
                if (ok1) {
                    __half2 h = __floats2half2_rn(gelu_exact(v10),
                                                  gelu_exact(v11));
                    *reinterpret_cast<__half2*>(dst + (size_t)r1 * ND + col) = h;
                }
            } else if (MODE == 1) {
                float w0 = g_w_of_row[r0], w1 = g_w_of_row[r1];
                float2 o0 = { v00 * w0, v01 * w0 };
                float2 o1 = { v10 * w1, v11 * w1 };
                *reinterpret_cast<float2*>(OutF + (size_t)r0 * ND + col) = o0;
                *reinterpret_cast<float2*>(OutF + (size_t)r1 * ND + col) = o1;
            } else { // MODE 3
                if (r0 < TOK) {
                    float o0 = v00, o1 = v01;
                    #pragma unroll
                    for (int k = 0; k < TOPK; k++) {
                        int rr = g_rows_of_tok[r0 * TOPK + k];
                        float2 e = *reinterpret_cast<const float2*>(
                            g_EO + (size_t)rr * DDIM + col);
                        o0 += e.x; o1 += e.y;
                    }
                    float2 o = { o0, o1 };
                    *reinterpret_cast<float2*>(OutF + (size_t)r0 * ND + col) = o;
                }
                if (r1 < TOK) {
                    float o0 = v10, o1 = v11;
                    #pragma unroll
                    for (int k = 0; k < TOPK; k++) {
                        int rr = g_rows_of_tok[r1 * TOPK + k];
                        float2 e = *reinterpret_cast<const float2*>(
                            g_EO + (size_t)rr * DDIM + col);
                        o0 += e.x; o1 += e.y;
                    }
                    float2 o = { o0, o1 };
                    *reinterpret_cast<float2*>(OutF + (size_t)r1 * ND + col) = o;
                }
            }
        }
    }
}

// ---------------------------------------------------------------------------
extern "C" void kernel_launch(void* const* d_in, const int* in_sizes, int n_in,
                              void* d_out, int out_size)
{
    const float* x      = (const float*)d_in[0];
    const float* gate_w = (const float*)d_in[1];
    const float* gate_b = (const float*)d_in[2];
    const float* w1     = (const float*)d_in[3];
    const float* b1     = (const float*)d_in[4];
    const float* w2     = (const float*)d_in[5];
    const float* b2     = (const float*)d_in[6];
    const float* ws1    = (const float*)d_in[7];
    const float* bs1    = (const float*)d_in[8];
    const float* ws2    = (const float*)d_in[9];
    const float* bs2    = (const float*)d_in[10];
    float* out = (float*)d_out;

    __half *xb, *w1b, *w2b, *ws1b, *ws2b, *Hb, *Hsb;
    float  *EOp;
    cudaGetSymbolAddress((void**)&xb,   g_xb);
    cudaGetSymbolAddress((void**)&w1b,  g_w1b);
    cudaGetSymbolAddress((void**)&w2b,  g_w2b);
    cudaGetSymbolAddress((void**)&ws1b, g_ws1b);
    cudaGetSymbolAddress((void**)&ws2b, g_ws2b);
    cudaGetSymbolAddress((void**)&Hb,   g_Hb);
    cudaGetSymbolAddress((void**)&Hsb,  g_Hsb);
    cudaGetSymbolAddress((void**)&EOp,  g_EO);

    cudaFuncSetAttribute(hgemm_kernel<0, DDIM, HDIM>,
                         cudaFuncAttributeMaxDynamicSharedMemorySize, DSM_BYTES);
    cudaFuncSetAttribute(hgemm_kernel<1, HDIM, DDIM>,
                         cudaFuncAttributeMaxDynamicSharedMemorySize, DSM_BYTES);
    cudaFuncSetAttribute(hgemm_kernel<3, HDIM, DDIM>,
                         cudaFuncAttributeMaxDynamicSharedMemorySize, DSM_BYTES);

    init_kernel<<<(MAXR + 255) / 256, 256>>>();
    gate_kernel<<<TOK, 128>>>(x, gate_w, gate_b);
    offsets_aux_kernel<<<1, 32>>>(out, out_size);
    scatter_kernel<<<(TOK * TOPK + 255) / 256, 256>>>();
    convert_w_kernel<<<(NC_TOT + 255) / 256, 256>>>(w1, w2, ws1, ws2);

    // merged layer1: expert tiles [0,MT) + shared tiles [MT, MT+TS_TILES)
    {
        dim3 grid(MT + TS_TILES, HDIM / BN);
        hgemm_kernel<0, DDIM, HDIM><<<grid, 256, DSM_BYTES>>>(
            xb, w1b, b1, ws1b, bs1, Hb, Hsb, nullptr);
    }
    // expert layer2
    {
        dim3 grid(MT, DDIM / BN);
        hgemm_kernel<1, HDIM, DDIM><<<grid, 256, DSM_BYTES>>>(
            Hb, w2b, b2, nullptr, nullptr, nullptr, nullptr, EOp);
    }
    // shared layer2 + combine
    {
        dim3 grid(TS_TILES, DDIM / BN);
        hgemm_kernel<3, HDIM, DDIM><<<grid, 256, DSM_BYTES>>>(
            Hsb, ws2b, bs2, nullptr, nullptr, nullptr, nullptr, out);
    }
}

// round 13
// speedup vs baseline: 1.6401x; 1.6401x over previous
#include <cuda_runtime.h>
#include <cuda_fp16.h>
#include <math.h>

// ---------------------------------------------------------------------------
// GeoMoE: sigmoid-gated top-3 MoE (E=23) + shared expert.
// fp16 tensor-core grouped GEMMs (mma.sync m16n8k16, fp32 accum).
// BM=128, BN=128, BK=32; 128 threads, warp tile 64x64, 2 CTAs/SM.
// ---------------------------------------------------------------------------

#define TOK   3136
#define DDIM  1024
#define HDIM  768
#define NE    23
#define TOPK  3

#define BM 128
#define BN 128
#define BK 32
#define MT 97
#define MAXR (MT * BM)
#define TS_TILES ((TOK + BM - 1) / BM)   // 25 shared-expert tiles

#define AS_STRIDE (BK + 8)    // 40 halfs = 80 B
#define BS_STRIDE (BN + 8)    // 136 halfs = 272 B
#define NSTAGE 4
#define DSM_BYTES (NSTAGE * (BM * AS_STRIDE + BK * BS_STRIDE) * 2)  // 75776

// ---------------- scratch (device globals; no allocation) ------------------
__device__ int   g_counts[NE];
__device__ float g_P[NE];
__device__ int   g_off[NE + 1];
__device__ int   g_topk_e[TOK * TOPK];
__device__ int   g_topk_rank[TOK * TOPK];
__device__ float g_topk_w[TOK * TOPK];
__device__ int   g_tok_of_row[MAXR];
__device__ float g_w_of_row[MAXR];
__device__ int   g_rows_of_tok[TOK * TOPK];

__device__ __align__(16) __half g_zero[DDIM];          // stays zero
__device__ __align__(16) __half g_xb  [TOK * DDIM];
__device__ __align__(16) __half g_w1b [NE * DDIM * HDIM];
__device__ __align__(16) __half g_w2b [NE * HDIM * DDIM];
__device__ __align__(16) __half g_ws1b[DDIM * HDIM];
__device__ __align__(16) __half g_ws2b[HDIM * DDIM];
__device__ __align__(16) __half g_Hb  [MAXR * HDIM];
__device__ __align__(16) __half g_Hsb [TOK * HDIM];
__device__ __align__(16) float  g_EO  [MAXR * DDIM];

__device__ __forceinline__ float gelu_exact(float v) {
    return 0.5f * v * (1.0f + erff(v * 0.70710678118654752f));
}

// ---------------------- fused fp32 -> fp16 (weights only) -------------------
#define NC_W1  (NE * DDIM * HDIM / 8)
#define NC_W2  (NE * HDIM * DDIM / 8)
#define NC_WS1 (DDIM * HDIM / 8)
#define NC_WS2 (HDIM * DDIM / 8)
#define NC_TOT (NC_W1 + NC_W2 + NC_WS1 + NC_WS2)

__device__ __forceinline__ void conv8(const float* __restrict__ s,
                                      __half* __restrict__ d, int i) {
    float4 a = reinterpret_cast<const float4*>(s)[2 * i + 0];
    float4 b = reinterpret_cast<const float4*>(s)[2 * i + 1];
    __half2 h0 = __floats2half2_rn(a.x, a.y);
    __half2 h1 = __floats2half2_rn(a.z, a.w);
    __half2 h2 = __floats2half2_rn(b.x, b.y);
    __half2 h3 = __floats2half2_rn(b.z, b.w);
    uint4 o;
    o.x = *reinterpret_cast<unsigned*>(&h0);
    o.y = *reinterpret_cast<unsigned*>(&h1);
    o.z = *reinterpret_cast<unsigned*>(&h2);
    o.w = *reinterpret_cast<unsigned*>(&h3);
    reinterpret_cast<uint4*>(d)[i] = o;
}

__global__ void convert_w_kernel(const float* __restrict__ w1,
                                 const float* __restrict__ w2,
                                 const float* __restrict__ ws1,
                                 const float* __restrict__ ws2) {
    int i = blockIdx.x * blockDim.x + threadIdx.x;
    if (i >= NC_TOT) return;
    if (i < NC_W1) { conv8(w1, g_w1b, i); return; }
    i -= NC_W1;
    if (i < NC_W2) { conv8(w2, g_w2b, i); return; }
    i -= NC_W2;
    if (i < NC_WS1) { conv8(ws1, g_ws1b, i); return; }
    i -= NC_WS1;
    conv8(ws2, g_ws2b, i);
}

// ---------------------------- init ------------------------------------------
__global__ void init_kernel() {
    int i = blockIdx.x * blockDim.x + threadIdx.x;
    if (i < MAXR) { g_tok_of_row[i] = -1; g_w_of_row[i] = 0.0f; }
    if (i < NE)   { g_counts[i] = 0; g_P[i] = 0.0f; }
}

// ---------------------- gating (+ x fp32->fp16 fused) -----------------------
__global__ __launch_bounds__(128) void gate_kernel(
    const float* __restrict__ x, const float* __restrict__ gw,
    const float* __restrict__ gb)
{
    __shared__ float s_x[DDIM];
    __shared__ float s_red[4][NE];
    __shared__ float s_gw[NE];

    const int t = blockIdx.x, tid = threadIdx.x, wid = tid >> 5;
    const float* xr = x + (size_t)t * DDIM;
    for (int i = tid; i < DDIM; i += 128) s_x[i] = xr[i];
    __syncthreads();

    {
        __half2* xo = reinterpret_cast<__half2*>(g_xb + (size_t)t * DDIM);
        #pragma unroll
        for (int j = 0; j < 4; j++) {
            int i2 = tid + j * 128;
            xo[i2] = __floats2half2_rn(s_x[2 * i2], s_x[2 * i2 + 1]);
        }
    }

    float acc[NE];
    #pragma unroll
    for (int e = 0; e < NE; e++) acc[e] = 0.0f;
    for (int k = tid; k < DDIM; k += 128) {
        float xv = s_x[k];
        const float* gr = gw + (size_t)k * NE;
        #pragma unroll
        for (int e = 0; e < NE; e++) acc[e] += xv * gr[e];
    }
    #pragma unroll
    for (int e = 0; e < NE; e++) {
        #pragma unroll
        for (int o = 16; o > 0; o >>= 1)
            acc[e] += __shfl_xor_sync(0xffffffffu, acc[e], o);
    }
    if ((tid & 31) == 0) {
        #pragma unroll
        for (int e = 0; e < NE; e++) s_red[wid][e] = acc[e];
    }
    __syncthreads();

    if (tid < NE) {
        float z = s_red[0][tid] + s_red[1][tid] + s_red[2][tid] + s_red[3][tid]
                  + gb[tid];
        s_gw[tid] = 1.0f / (1.0f + expf(-z));
    }
    __syncthreads();

    if (tid < NE) {
        float sum = 0.0f;
        #pragma unroll
        for (int e = 0; e < NE; e++) sum += s_gw[e];
        atomicAdd(&g_P[tid], s_gw[tid] / sum);
    }

    if (tid == 0) {
        float v0 = -1.f, v1 = -1.f, v2 = -1.f;
        int   i0 = 0,    i1 = 0,    i2 = 0;
        #pragma unroll
        for (int e = 0; e < NE; e++) {
            float v = s_gw[e];
            if (v > v0)      { v2=v1; i2=i1; v1=v0; i1=i0; v0=v; i0=e; }
            else if (v > v1) { v2=v1; i2=i1; v1=v;  i1=e; }
            else if (v > v2) { v2=v;  i2=e; }
        }
        float s3 = v0 + v1 + v2;
        int   ids[TOPK] = { i0, i1, i2 };
        float vs [TOPK] = { v0, v1, v2 };
        #pragma unroll
        for (int k = 0; k < TOPK; k++) {
            int rank = atomicAdd(&g_counts[ids[k]], 1);
            int idx  = t * TOPK + k;
            g_topk_e[idx]    = ids[k];
            g_topk_rank[idx] = rank;
            g_topk_w[idx]    = vs[k] / s3;
        }
    }
}

// -------------------- offsets (padded) + aux loss ----------------------------
__global__ void offsets_aux_kernel(float* __restrict__ out, int out_size) {
    if (threadIdx.x == 0) {
        int acc = 0;
        g_off[0] = 0;
        float aux = 0.0f;
        #pragma unroll
        for (int e = 0; e < NE; e++) {
            int c = g_counts[e];
            acc += ((c + BM - 1) / BM) * BM;
            g_off[e + 1] = acc;
            float P = g_P[e] / (float)TOK;
            float F = (float)NE * (float)c / (float)(TOPK * TOK);
            aux += P * F;
        }
        if (out_size > TOK * DDIM) out[TOK * DDIM] = aux;
    }
}

// ------------------------------ scatter --------------------------------------
__global__ void scatter_kernel() {
    int idx = blockIdx.x * blockDim.x + threadIdx.x;
    if (idx >= TOK * TOPK) return;
    int e   = g_topk_e[idx];
    int row = g_off[e] + g_topk_rank[idx];
    g_tok_of_row[row] = idx / TOPK;
    g_w_of_row[row]   = g_topk_w[idx];
    g_rows_of_tok[idx] = row;
}

// ------------------------------ fp16 GEMM ------------------------------------
// MODE 0 (merged L1):
//   bx <  MT: Hb  = gelu(gather(xb) @ w1b[e] + b1[e])    KD=1024 ND=768
//   bx >= MT: Hsb = gelu(xb @ ws1b + bs1)
// MODE 1: EO  = (Hb @ w2b[e] + b2[e]) * w_of_row         KD=768  ND=1024
// MODE 3: out = Hsb @ ws2b + bs2 + sum_k EO[rows_of_tok] KD=768  ND=1024

#define CP_ASYNC16(dst, src) \
    asm volatile("cp.async.cg.shared.global [%0], [%1], 16;\n" \
                 :: "r"(dst), "l"(src))
#define CP_COMMIT() asm volatile("cp.async.commit_group;\n")
#define CP_WAIT2()  asm volatile("cp.async.wait_group 2;\n")
#define CP_WAIT1()  asm volatile("cp.async.wait_group 1;\n")
#define CP_WAIT0()  asm volatile("cp.async.wait_group 0;\n")

#define LDMX4(r0,r1,r2,r3,addr) \
    asm volatile("ldmatrix.sync.aligned.m8n8.x4.shared.b16 {%0,%1,%2,%3}, [%4];\n" \
        : "=r"(r0),"=r"(r1),"=r"(r2),"=r"(r3) : "r"(addr))
#define LDMX4T(r0,r1,r2,r3,addr) \
    asm volatile("ldmatrix.sync.aligned.m8n8.x4.trans.shared.b16 {%0,%1,%2,%3}, [%4];\n" \
        : "=r"(r0),"=r"(r1),"=r"(r2),"=r"(r3) : "r"(addr))
#define MMA16816(c0,c1,c2,c3,a0,a1,a2,a3,b0,b1) \
    asm volatile("mma.sync.aligned.m16n8k16.row.col.f32.f16.f16.f32 " \
        "{%0,%1,%2,%3}, {%4,%5,%6,%7}, {%8,%9}, {%0,%1,%2,%3};\n" \
        : "+f"(c0),"+f"(c1),"+f"(c2),"+f"(c3) \
        : "r"(a0),"r"(a1),"r"(a2),"r"(a3), "r"(b0),"r"(b1))

template<int MODE, int KD, int ND>
__global__ __launch_bounds__(128, 2) void hgemm_kernel(
    const __half* __restrict__ A,
    const __half* __restrict__ W,
    const float*  __restrict__ bias,
    const __half* __restrict__ Ws,     // MODE 0 shared-branch weights
    const float*  __restrict__ bs,     // MODE 0 shared-branch bias
    __half* __restrict__ OutH,         // MODE 0 expert out (Hb)
    __half* __restrict__ OutHs,        // MODE 0 shared out (Hsb)
    float*  __restrict__ OutF)
{
    extern __shared__ __half dsm[];
    const int n0 = blockIdx.y * BN;

    bool shared_part = (MODE == 0) && ((int)blockIdx.x >= MT);
    int m0;
    const __half* Wp;
    const float*  bp;
    if (MODE == 0 && shared_part) {
        m0 = ((int)blockIdx.x - MT) * BM;
        Wp = Ws; bp = bs;
    } else if (MODE == 0 || MODE == 1) {
        m0 = blockIdx.x * BM;
        if (m0 >= g_off[NE]) return;
        int e = 0;
        while (m0 >= g_off[e + 1]) e++;
        Wp = W + (size_t)e * KD * ND;
        bp = bias + (size_t)e * ND;
    } else {
        m0 = blockIdx.x * BM;
        Wp = W; bp = bias;
    }

    const int tid  = threadIdx.x;
    const int lane = tid & 31;
    const int wid  = tid >> 5;          // 0..3
    const int wm   = (wid >> 1) * 64;   // 2 warps along M
    const int wn   = (wid & 1) * 64;    // 2 warps along N

    // A loader: thread covers rows (tid>>2) + 32j (j=0..3), 16B chunk at ac
    const int arow = tid >> 2;          // 0..31
    const int ac   = (tid & 3) * 8;     // 0..24 halfs
    const __half* aptr[4];
    #pragma unroll
    for (int j = 0; j < 4; j++) {
        int r = m0 + arow + 32 * j;
        if (MODE == 0 && !shared_part) {
            int tk = g_tok_of_row[r];
            aptr[j] = ((tk >= 0) ? A + (size_t)tk * KD : g_zero) + ac;
        } else if (MODE == 1) {
            aptr[j] = A + (size_t)r * KD + ac;
        } else {
            aptr[j] = ((r < TOK) ? A + (size_t)r * KD : g_zero) + ac;
        }
    }
    // B loader: thread covers rows (tid>>4) + 8j (j=0..3), 16B chunk at bc
    const int brow = tid >> 4;          // 0..7
    const int bc   = (tid & 15) * 8;    // 0..120 halfs
    const __half* bptr = Wp + (size_t)brow * ND + n0 + bc;

    const unsigned as_base = (unsigned)__cvta_generic_to_shared(&dsm[0]);
    const unsigned bs_base = as_base + (unsigned)(NSTAGE * BM * AS_STRIDE) * 2;
    unsigned aDst[4];
    #pragma unroll
    for (int j = 0; j < 4; j++)
        aDst[j] = as_base + (unsigned)((arow + 32 * j) * AS_STRIDE + ac) * 2;
    const unsigned bDst = bs_base + (unsigned)(brow * BS_STRIDE + bc) * 2;
    const unsigned aBufSz = (unsigned)(BM * AS_STRIDE) * 2;
    const unsigned bBufSz = (unsigned)(BK * BS_STRIDE) * 2;

    float acc[4][8][4];
    #pragma unroll
    for (int i = 0; i < 4; i++)
        #pragma unroll
        for (int j = 0; j < 8; j++)
            #pragma unroll
            for (int k = 0; k < 4; k++) acc[i][j][k] = 0.0f;

    const int NK = KD / BK;

    // prologue: stages 0..2 (3 groups in flight, 4 buffers)
    #pragma unroll
    for (int s = 0; s < 3; s++) {
        unsigned ab = s * aBufSz, bb = s * bBufSz;
        int k0 = s * BK;
        #pragma unroll
        for (int j = 0; j < 4; j++)
            CP_ASYNC16(aDst[j] + ab, aptr[j] + k0);
        #pragma unroll
        for (int j = 0; j < 4; j++)
            CP_ASYNC16(bDst + bb + (unsigned)(j * 8 * BS_STRIDE) * 2,
                       bptr + (size_t)(k0 + j * 8) * ND);
        CP_COMMIT();
    }

    // ldmatrix source addresses (per warp lane)
    const unsigned aLdm = as_base +
        (unsigned)((wm + (lane & 15)) * AS_STRIDE + (lane >> 4) * 8) * 2;
    const unsigned bLdm = bs_base +
        (unsigned)((lane & 15) * BS_STRIDE + wn + (lane >> 4) * 8) * 2;

    for (int ks = 0; ks < NK; ks++) {
        const int rem = NK - 1 - ks;
        if (rem >= 2)      { CP_WAIT2(); }
        else if (rem == 1) { CP_WAIT1(); }
        else               { CP_WAIT0(); }
        __syncthreads();

        if (ks + 3 < NK) {
            int sb = (ks + 3) % NSTAGE;
            unsigned ab = sb * aBufSz, bb = sb * bBufSz;
            int k0 = (ks + 3) * BK;
            #pragma unroll
            for (int j = 0; j < 4; j++)
                CP_ASYNC16(aDst[j] + ab, aptr[j] + k0);
            #pragma unroll
            for (int j = 0; j < 4; j++)
                CP_ASYNC16(bDst + bb + (unsigned)(j * 8 * BS_STRIDE) * 2,
                           bptr + (size_t)(k0 + j * 8) * ND);
            CP_COMMIT();
        }

        const int buf = ks % NSTAGE;
        const unsigned abuf = buf * aBufSz;
        const unsigned bbuf = buf * bBufSz;

        #pragma unroll
        for (int kst = 0; kst < 2; kst++) {
            unsigned aF[4][4], bF[4][4];
            #pragma unroll
            for (int mt = 0; mt < 4; mt++) {
                unsigned addr = aLdm + abuf +
                    (unsigned)(mt * 16 * AS_STRIDE + kst * 16) * 2;
                LDMX4(aF[mt][0], aF[mt][1], aF[mt][2], aF[mt][3], addr);
            }
            #pragma unroll
            for (int nt = 0; nt < 4; nt++) {
                unsigned addr = bLdm + bbuf +
                    (unsigned)(kst * 16 * BS_STRIDE + nt * 16) * 2;
                LDMX4T(bF[nt][0], bF[nt][1], bF[nt][2], bF[nt][3], addr);
            }
            #pragma unroll
            for (int mt = 0; mt < 4; mt++)
                #pragma unroll
                for (int n8 = 0; n8 < 8; n8++) {
                    unsigned b0 = bF[n8 >> 1][(n8 & 1) * 2];
                    unsigned b1 = bF[n8 >> 1][(n8 & 1) * 2 + 1];
                    MMA16816(acc[mt][n8][0], acc[mt][n8][1],
                             acc[mt][n8][2], acc[mt][n8][3],
                             aF[mt][0], aF[mt][1], aF[mt][2], aF[mt][3],
                             b0, b1);
                }
        }
    }

    // ------------------------------ epilogue --------------------------------
    const int gID = lane >> 2;
    const int tig = lane & 3;
    #pragma unroll
    for (int mt = 0; mt < 4; mt++) {
        #pragma unroll
        for (int n8 = 0; n8 < 8; n8++) {
            const int col = n0 + wn + n8 * 8 + tig * 2;
            const float2 bb = *reinterpret_cast<const float2*>(bp + col);
            const int r0 = m0 + wm + mt * 16 + gID;
            const int r1 = r0 + 8;
            float v00 = acc[mt][n8][0] + bb.x;
            float v01 = acc[mt][n8][1] + bb.y;
            float v10 = acc[mt][n8][2] + bb.x;
            float v11 = acc[mt][n8][3] + bb.y;

            if (MODE == 0) {
                __half* dst = shared_part ? OutHs : OutH;
                bool ok0 = shared_part ? (r0 < TOK) : true;
                bool ok1 = shared_part ? (r1 < TOK) : true;
                if (ok0) {
                    __half2 h = __floats2half2_rn(gelu_exact(v00),
                                                  gelu_exact(v01));
                    *reinterpret_cast<__half2*>(dst + (size_t)r0 * ND + col) = h;
                }
                if (ok1) {
                    __half2 h = __floats2half2_rn(gelu_exact(v10),
                                                  gelu_exact(v11));
                    *reinterpret_cast<__half2*>(dst + (size_t)r1 * ND + col) = h;
                }
            } else if (MODE == 1) {
                float w0 = g_w_of_row[r0], w1 = g_w_of_row[r1];
                float2 o0 = { v00 * w0, v01 * w0 };
                float2 o1 = { v10 * w1, v11 * w1 };
                *reinterpret_cast<float2*>(OutF + (size_t)r0 * ND + col) = o0;
                *reinterpret_cast<float2*>(OutF + (size_t)r1 * ND + col) = o1;
            } else { // MODE 3
                if (r0 < TOK) {
                    float o0 = v00, o1 = v01;
                    #pragma unroll
                    for (int k = 0; k < TOPK; k++) {
                        int rr = g_rows_of_tok[r0 * TOPK + k];
                        float2 e = *reinterpret_cast<const float2*>(
                            g_EO + (size_t)rr * DDIM + col);
                        o0 += e.x; o1 += e.y;
                    }
                    float2 o = { o0, o1 };
                    *reinterpret_cast<float2*>(OutF + (size_t)r0 * ND + col) = o;
                }
                if (r1 < TOK) {
                    float o0 = v10, o1 = v11;
                    #pragma unroll
                    for (int k = 0; k < TOPK; k++) {
                        int rr = g_rows_of_tok[r1 * TOPK + k];
                        float2 e = *reinterpret_cast<const float2*>(
                            g_EO + (size_t)rr * DDIM + col);
                        o0 += e.x; o1 += e.y;
                    }
                    float2 o = { o0, o1 };
                    *reinterpret_cast<float2*>(OutF + (size_t)r1 * ND + col) = o;
                }
            }
        }
    }
}

// ---------------------------------------------------------------------------
extern "C" void kernel_launch(void* const* d_in, const int* in_sizes, int n_in,
                              void* d_out, int out_size)
{
    const float* x      = (const float*)d_in[0];
    const float* gate_w = (const float*)d_in[1];
    const float* gate_b = (const float*)d_in[2];
    const float* w1     = (const float*)d_in[3];
    const float* b1     = (const float*)d_in[4];
    const float* w2     = (const float*)d_in[5];
    const float* b2     = (const float*)d_in[6];
    const float* ws1    = (const float*)d_in[7];
    const float* bs1    = (const float*)d_in[8];
    const float* ws2    = (const float*)d_in[9];
    const float* bs2    = (const float*)d_in[10];
    float* out = (float*)d_out;

    __half *xb, *w1b, *w2b, *ws1b, *ws2b, *Hb, *Hsb;
    float  *EOp;
    cudaGetSymbolAddress((void**)&xb,   g_xb);
    cudaGetSymbolAddress((void**)&w1b,  g_w1b);
    cudaGetSymbolAddress((void**)&w2b,  g_w2b);
    cudaGetSymbolAddress((void**)&ws1b, g_ws1b);
    cudaGetSymbolAddress((void**)&ws2b, g_ws2b);
    cudaGetSymbolAddress((void**)&Hb,   g_Hb);
    cudaGetSymbolAddress((void**)&Hsb,  g_Hsb);
    cudaGetSymbolAddress((void**)&EOp,  g_EO);

    cudaFuncSetAttribute(hgemm_kernel<0, DDIM, HDIM>,
                         cudaFuncAttributeMaxDynamicSharedMemorySize, DSM_BYTES);
    cudaFuncSetAttribute(hgemm_kernel<1, HDIM, DDIM>,
                         cudaFuncAttributeMaxDynamicSharedMemorySize, DSM_BYTES);
    cudaFuncSetAttribute(hgemm_kernel<3, HDIM, DDIM>,
                         cudaFuncAttributeMaxDynamicSharedMemorySize, DSM_BYTES);

    init_kernel<<<(MAXR + 255) / 256, 256>>>();
    gate_kernel<<<TOK, 128>>>(x, gate_w, gate_b);
    offsets_aux_kernel<<<1, 32>>>(out, out_size);
    scatter_kernel<<<(TOK * TOPK + 255) / 256, 256>>>();
    convert_w_kernel<<<(NC_TOT + 255) / 256, 256>>>(w1, w2, ws1, ws2);

    // merged layer1: expert tiles [0,MT) + shared tiles [MT, MT+TS_TILES)
    {
        dim3 grid(MT + TS_TILES, HDIM / BN);
        hgemm_kernel<0, DDIM, HDIM><<<grid, 128, DSM_BYTES>>>(
            xb, w1b, b1, ws1b, bs1, Hb, Hsb, nullptr);
    }
    // expert layer2
    {
        dim3 grid(MT, DDIM / BN);
        hgemm_kernel<1, HDIM, DDIM><<<grid, 128, DSM_BYTES>>>(
            Hb, w2b, b2, nullptr, nullptr, nullptr, nullptr, EOp);
    }
    // shared layer2 + combine
    {
        dim3 grid(TS_TILES, DDIM / BN);
        hgemm_kernel<3, HDIM, DDIM><<<grid, 128, DSM_BYTES>>>(
            Hsb, ws2b, bs2, nullptr, nullptr, nullptr, nullptr, out);
    }
}

// round 17
// speedup vs baseline: 1.8630x; 1.1359x over previous
#include <cuda_runtime.h>
#include <cuda_fp16.h>
#include <math.h>

// ---------------------------------------------------------------------------
// GeoMoE: sigmoid-gated top-3 MoE (E=23) + shared expert.
// fp16 tensor-core grouped GEMMs (mma.sync m16n8k16, fp32 accum).
// BM=64 (pad-64 expert groups), BN=128, BK=32; 128 thr, warp 32x64, 3 CTA/SM.
// ---------------------------------------------------------------------------

#define TOK   3136
#define DDIM  1024
#define HDIM  768
#define NE    23
#define TOPK  3

#define BM 64
#define BN 128
#define BK 32
#define MT 170                            // max 64-row expert tiles
#define MAXR (MT * BM)                    // 10880 padded rows
#define TS_TILES ((TOK + BM - 1) / BM)    // 49 shared-expert tiles

#define AS_STRIDE (BK + 8)    // 40 halfs = 80 B
#define BS_STRIDE (BN + 8)    // 136 halfs = 272 B
#define NSTAGE 4
#define DSM_BYTES (NSTAGE * (BM * AS_STRIDE + BK * BS_STRIDE) * 2)  // 55296

// ---------------- scratch (device globals; no allocation) ------------------
__device__ int   g_counts[NE];
__device__ float g_P[NE];
__device__ int   g_off[NE + 1];
__device__ int   g_topk_e[TOK * TOPK];
__device__ int   g_topk_rank[TOK * TOPK];
__device__ float g_topk_w[TOK * TOPK];
__device__ int   g_tok_of_row[MAXR];
__device__ float g_w_of_row[MAXR];
__device__ int   g_rows_of_tok[TOK * TOPK];

__device__ __align__(16) __half g_zero[DDIM];          // stays zero
__device__ __align__(16) __half g_xb  [TOK * DDIM];
__device__ __align__(16) __half g_w1b [NE * DDIM * HDIM];
__device__ __align__(16) __half g_w2b [NE * HDIM * DDIM];
__device__ __align__(16) __half g_ws1b[DDIM * HDIM];
__device__ __align__(16) __half g_ws2b[HDIM * DDIM];
__device__ __align__(16) __half g_Hb  [MAXR * HDIM];
__device__ __align__(16) __half g_Hsb [TOK * HDIM];
__device__ __align__(16) float  g_EO  [MAXR * DDIM];

__device__ __forceinline__ float gelu_exact(float v) {
    return 0.5f * v * (1.0f + erff(v * 0.70710678118654752f));
}

// ---------------------- fused fp32 -> fp16 (weights only) -------------------
#define NC_W1  (NE * DDIM * HDIM / 8)
#define NC_W2  (NE * HDIM * DDIM / 8)
#define NC_WS1 (DDIM * HDIM / 8)
#define NC_WS2 (HDIM * DDIM / 8)
#define NC_TOT (NC_W1 + NC_W2 + NC_WS1 + NC_WS2)

__device__ __forceinline__ void conv8(const float* __restrict__ s,
                                      __half* __restrict__ d, int i) {
    float4 a = reinterpret_cast<const float4*>(s)[2 * i + 0];
    float4 b = reinterpret_cast<const float4*>(s)[2 * i + 1];
    __half2 h0 = __floats2half2_rn(a.x, a.y);
    __half2 h1 = __floats2half2_rn(a.z, a.w);
    __half2 h2 = __floats2half2_rn(b.x, b.y);
    __half2 h3 = __floats2half2_rn(b.z, b.w);
    uint4 o;
    o.x = *reinterpret_cast<unsigned*>(&h0);
    o.y = *reinterpret_cast<unsigned*>(&h1);
    o.z = *reinterpret_cast<unsigned*>(&h2);
    o.w = *reinterpret_cast<unsigned*>(&h3);
    reinterpret_cast<uint4*>(d)[i] = o;
}

__global__ void convert_w_kernel(const float* __restrict__ w1,
                                 const float* __restrict__ w2,
                                 const float* __restrict__ ws1,
                                 const float* __restrict__ ws2) {
    int i = blockIdx.x * blockDim.x + threadIdx.x;
    if (i >= NC_TOT) return;
    if (i < NC_W1) { conv8(w1, g_w1b, i); return; }
    i -= NC_W1;
    if (i < NC_W2) { conv8(w2, g_w2b, i); return; }
    i -= NC_W2;
    if (i < NC_WS1) { conv8(ws1, g_ws1b, i); return; }
    i -= NC_WS1;
    conv8(ws2, g_ws2b, i);
}

// ---------------------------- init ------------------------------------------
__global__ void init_kernel() {
    int i = blockIdx.x * blockDim.x + threadIdx.x;
    if (i < MAXR) { g_tok_of_row[i] = -1; g_w_of_row[i] = 0.0f; }
    if (i < NE)   { g_counts[i] = 0; g_P[i] = 0.0f; }
}

// ---------------------- gating (+ x fp32->fp16 fused) -----------------------
__global__ __launch_bounds__(128) void gate_kernel(
    const float* __restrict__ x, const float* __restrict__ gw,
    const float* __restrict__ gb)
{
    __shared__ float s_x[DDIM];
    __shared__ float s_red[4][NE];
    __shared__ float s_gw[NE];

    const int t = blockIdx.x, tid = threadIdx.x, wid = tid >> 5;
    const float* xr = x + (size_t)t * DDIM;
    for (int i = tid; i < DDIM; i += 128) s_x[i] = xr[i];
    __syncthreads();

    {
        __half2* xo = reinterpret_cast<__half2*>(g_xb + (size_t)t * DDIM);
        #pragma unroll
        for (int j = 0; j < 4; j++) {
            int i2 = tid + j * 128;
            xo[i2] = __floats2half2_rn(s_x[2 * i2], s_x[2 * i2 + 1]);
        }
    }

    float acc[NE];
    #pragma unroll
    for (int e = 0; e < NE; e++) acc[e] = 0.0f;
    for (int k = tid; k < DDIM; k += 128) {
        float xv = s_x[k];
        const float* gr = gw + (size_t)k * NE;
        #pragma unroll
        for (int e = 0; e < NE; e++) acc[e] += xv * gr[e];
    }
    #pragma unroll
    for (int e = 0; e < NE; e++) {
        #pragma unroll
        for (int o = 16; o > 0; o >>= 1)
            acc[e] += __shfl_xor_sync(0xffffffffu, acc[e], o);
    }
    if ((tid & 31) == 0) {
        #pragma unroll
        for (int e = 0; e < NE; e++) s_red[wid][e] = acc[e];
    }
    __syncthreads();

    if (tid < NE) {
        float z = s_red[0][tid] + s_red[1][tid] + s_red[2][tid] + s_red[3][tid]
                  + gb[tid];
        s_gw[tid] = 1.0f / (1.0f + expf(-z));
    }
    __syncthreads();

    if (tid < NE) {
        float sum = 0.0f;
        #pragma unroll
        for (int e = 0; e < NE; e++) sum += s_gw[e];
        atomicAdd(&g_P[tid], s_gw[tid] / sum);
    }

    if (tid == 0) {
        float v0 = -1.f, v1 = -1.f, v2 = -1.f;
        int   i0 = 0,    i1 = 0,    i2 = 0;
        #pragma unroll
        for (int e = 0; e < NE; e++) {
            float v = s_gw[e];
            if (v > v0)      { v2=v1; i2=i1; v1=v0; i1=i0; v0=v; i0=e; }
            else if (v > v1) { v2=v1; i2=i1; v1=v;  i1=e; }
            else if (v > v2) { v2=v;  i2=e; }
        }
        float s3 = v0 + v1 + v2;
        int   ids[TOPK] = { i0, i1, i2 };
        float vs [TOPK] = { v0, v1, v2 };
        #pragma unroll
        for (int k = 0; k < TOPK; k++) {
            int rank = atomicAdd(&g_counts[ids[k]], 1);
            int idx  = t * TOPK + k;
            g_topk_e[idx]    = ids[k];
            g_topk_rank[idx] = rank;
            g_topk_w[idx]    = vs[k] / s3;
        }
    }
}

// -------------------- offsets (padded to 64) + aux loss ----------------------
__global__ void offsets_aux_kernel(float* __restrict__ out, int out_size) {
    if (threadIdx.x == 0) {
        int acc = 0;
        g_off[0] = 0;
        float aux = 0.0f;
        #pragma unroll
        for (int e = 0; e < NE; e++) {
            int c = g_counts[e];
            acc += ((c + BM - 1) / BM) * BM;
            g_off[e + 1] = acc;
            float P = g_P[e] / (float)TOK;
            float F = (float)NE * (float)c / (float)(TOPK * TOK);
            aux += P * F;
        }
        if (out_size > TOK * DDIM) out[TOK * DDIM] = aux;
    }
}

// ------------------------------ scatter --------------------------------------
__global__ void scatter_kernel() {
    int idx = blockIdx.x * blockDim.x + threadIdx.x;
    if (idx >= TOK * TOPK) return;
    int e   = g_topk_e[idx];
    int row = g_off[e] + g_topk_rank[idx];
    g_tok_of_row[row] = idx / TOPK;
    g_w_of_row[row]   = g_topk_w[idx];
    g_rows_of_tok[idx] = row;
}

// ------------------------------ fp16 GEMM ------------------------------------
// MODE 0 (merged L1):
//   bx <  MT: Hb  = gelu(gather(xb) @ w1b[e] + b1[e])    KD=1024 ND=768
//   bx >= MT: Hsb = gelu(xb @ ws1b + bs1)
// MODE 1: EO  = (Hb @ w2b[e] + b2[e]) * w_of_row         KD=768  ND=1024
// MODE 3: out = Hsb @ ws2b + bs2 + sum_k EO[rows_of_tok] KD=768  ND=1024

#define CP_ASYNC16(dst, src) \
    asm volatile("cp.async.cg.shared.global [%0], [%1], 16;\n" \
                 :: "r"(dst), "l"(src))
#define CP_COMMIT() asm volatile("cp.async.commit_group;\n")
#define CP_WAIT2()  asm volatile("cp.async.wait_group 2;\n")
#define CP_WAIT1()  asm volatile("cp.async.wait_group 1;\n")
#define CP_WAIT0()  asm volatile("cp.async.wait_group 0;\n")

#define LDMX4(r0,r1,r2,r3,addr) \
    asm volatile("ldmatrix.sync.aligned.m8n8.x4.shared.b16 {%0,%1,%2,%3}, [%4];\n" \
        : "=r"(r0),"=r"(r1),"=r"(r2),"=r"(r3) : "r"(addr))
#define LDMX4T(r0,r1,r2,r3,addr) \
    asm volatile("ldmatrix.sync.aligned.m8n8.x4.trans.shared.b16 {%0,%1,%2,%3}, [%4];\n" \
        : "=r"(r0),"=r"(r1),"=r"(r2),"=r"(r3) : "r"(addr))
#define MMA16816(c0,c1,c2,c3,a0,a1,a2,a3,b0,b1) \
    asm volatile("mma.sync.aligned.m16n8k16.row.col.f32.f16.f16.f32 " \
        "{%0,%1,%2,%3}, {%4,%5,%6,%7}, {%8,%9}, {%0,%1,%2,%3};\n" \
        : "+f"(c0),"+f"(c1),"+f"(c2),"+f"(c3) \
        : "r"(a0),"r"(a1),"r"(a2),"r"(a3), "r"(b0),"r"(b1))

template<int MODE, int KD, int ND>
__global__ __launch_bounds__(128, 3) void hgemm_kernel(
    const __half* __restrict__ A,
    const __half* __restrict__ W,
    const float*  __restrict__ bias,
    const __half* __restrict__ Ws,     // MODE 0 shared-branch weights
    const float*  __restrict__ bs,     // MODE 0 shared-branch bias
    __half* __restrict__ OutH,         // MODE 0 expert out (Hb)
    __half* __restrict__ OutHs,        // MODE 0 shared out (Hsb)
    float*  __restrict__ OutF)
{
    extern __shared__ __half dsm[];
    const int n0 = blockIdx.y * BN;

    bool shared_part = (MODE == 0) && ((int)blockIdx.x >= MT);
    int m0;
    const __half* Wp;
    const float*  bp;
    if (MODE == 0 && shared_part) {
        m0 = ((int)blockIdx.x - MT) * BM;
        Wp = Ws; bp = bs;
    } else if (MODE == 0 || MODE == 1) {
        m0 = blockIdx.x * BM;
        if (m0 >= g_off[NE]) return;
        int e = 0;
        while (m0 >= g_off[e + 1]) e++;
        Wp = W + (size_t)e * KD * ND;
        bp = bias + (size_t)e * ND;
    } else {
        m0 = blockIdx.x * BM;
        Wp = W; bp = bias;
    }

    const int tid  = threadIdx.x;
    const int lane = tid & 31;
    const int wid  = tid >> 5;          // 0..3
    const int wm   = (wid >> 1) * 32;   // 2 warps along M (tile 32)
    const int wn   = (wid & 1) * 64;    // 2 warps along N (tile 64)

    // A loader: thread covers rows (tid>>2) + 32j (j=0..1), 16B chunk at ac
    const int arow = tid >> 2;          // 0..31
    const int ac   = (tid & 3) * 8;     // 0..24 halfs
    const __half* aptr[2];
    #pragma unroll
    for (int j = 0; j < 2; j++) {
        int r = m0 + arow + 32 * j;
        if (MODE == 0 && !shared_part) {
            int tk = g_tok_of_row[r];
            aptr[j] = ((tk >= 0) ? A + (size_t)tk * KD : g_zero) + ac;
        } else if (MODE == 1) {
            aptr[j] = A + (size_t)r * KD + ac;
        } else {
            aptr[j] = ((r < TOK) ? A + (size_t)r * KD : g_zero) + ac;
        }
    }
    // B loader: thread covers rows (tid>>4) + 8j (j=0..3), 16B chunk at bc
    const int brow = tid >> 4;          // 0..7
    const int bc   = (tid & 15) * 8;    // 0..120 halfs
    const __half* bptr = Wp + (size_t)brow * ND + n0 + bc;

    const unsigned as_base = (unsigned)__cvta_generic_to_shared(&dsm[0]);
    const unsigned bs_base = as_base + (unsigned)(NSTAGE * BM * AS_STRIDE) * 2;
    unsigned aDst[2];
    #pragma unroll
    for (int j = 0; j < 2; j++)
        aDst[j] = as_base + (unsigned)((arow + 32 * j) * AS_STRIDE + ac) * 2;
    const unsigned bDst = bs_base + (unsigned)(brow * BS_STRIDE + bc) * 2;
    const unsigned aBufSz = (unsigned)(BM * AS_STRIDE) * 2;
    const unsigned bBufSz = (unsigned)(BK * BS_STRIDE) * 2;

    float acc[2][8][4];
    #pragma unroll
    for (int i = 0; i < 2; i++)
        #pragma unroll
        for (int j = 0; j < 8; j++)
            #pragma unroll
            for (int k = 0; k < 4; k++) acc[i][j][k] = 0.0f;

    const int NK = KD / BK;

    // prologue: stages 0..2 (3 groups in flight, 4 buffers)
    #pragma unroll
    for (int s = 0; s < 3; s++) {
        unsigned ab = s * aBufSz, bb = s * bBufSz;
        int k0 = s * BK;
        #pragma unroll
        for (int j = 0; j < 2; j++)
            CP_ASYNC16(aDst[j] + ab, aptr[j] + k0);
        #pragma unroll
        for (int j = 0; j < 4; j++)
            CP_ASYNC16(bDst + bb + (unsigned)(j * 8 * BS_STRIDE) * 2,
                       bptr + (size_t)(k0 + j * 8) * ND);
        CP_COMMIT();
    }

    // ldmatrix source addresses (per warp lane)
    const unsigned aLdm = as_base +
        (unsigned)((wm + (lane & 15)) * AS_STRIDE + (lane >> 4) * 8) * 2;
    const unsigned bLdm = bs_base +
        (unsigned)((lane & 15) * BS_STRIDE + wn + (lane >> 4) * 8) * 2;

    for (int ks = 0; ks < NK; ks++) {
        const int rem = NK - 1 - ks;
        if (rem >= 2)      { CP_WAIT2(); }
        else if (rem == 1) { CP_WAIT1(); }
        else               { CP_WAIT0(); }
        __syncthreads();

        if (ks + 3 < NK) {
            int sb = (ks + 3) % NSTAGE;
            unsigned ab = sb * aBufSz, bb = sb * bBufSz;
            int k0 = (ks + 3) * BK;
            #pragma unroll
            for (int j = 0; j < 2; j++)
                CP_ASYNC16(aDst[j] + ab, aptr[j] + k0);
            #pragma unroll
            for (int j = 0; j < 4; j++)
                CP_ASYNC16(bDst + bb + (unsigned)(j * 8 * BS_STRIDE) * 2,
                           bptr + (size_t)(k0 + j * 8) * ND);
            CP_COMMIT();
        }

        const int buf = ks % NSTAGE;
        const unsigned abuf = buf * aBufSz;
        const unsigned bbuf = buf * bBufSz;

        #pragma unroll
        for (int kst = 0; kst < 2; kst++) {
            unsigned aF[2][4], bF[4][4];
            #pragma unroll
            for (int mt = 0; mt < 2; mt++) {
                unsigned addr = aLdm + abuf +
                    (unsigned)(mt * 16 * AS_STRIDE + kst * 16) * 2;
                LDMX4(aF[mt][0], aF[mt][1], aF[mt][2], aF[mt][3], addr);
            }
            #pragma unroll
            for (int nt = 0; nt < 4; nt++) {
                unsigned addr = bLdm + bbuf +
                    (unsigned)(kst * 16 * BS_STRIDE + nt * 16) * 2;
                LDMX4T(bF[nt][0], bF[nt][1], bF[nt][2], bF[nt][3], addr);
            }
            #pragma unroll
            for (int mt = 0; mt < 2; mt++)
                #pragma unroll
                for (int n8 = 0; n8 < 8; n8++) {
                    unsigned b0 = bF[n8 >> 1][(n8 & 1) * 2];
                    unsigned b1 = bF[n8 >> 1][(n8 & 1) * 2 + 1];
                    MMA16816(acc[mt][n8][0], acc[mt][n8][1],
                             acc[mt][n8][2], acc[mt][n8][3],
                             aF[mt][0], aF[mt][1], aF[mt][2], aF[mt][3],
                             b0, b1);
                }
        }
    }

    // ------------------------------ epilogue --------------------------------
    const int gID = lane >> 2;
    const int tig = lane & 3;
    #pragma unroll
    for (int mt = 0; mt < 2; mt++) {
        #pragma unroll
        for (int n8 = 0; n8 < 8; n8++) {
            const int col = n0 + wn + n8 * 8 + tig * 2;
            const float2 bb = *reinterpret_cast<const float2*>(bp + col);
            const int r0 = m0 + wm + mt * 16 + gID;
            const int r1 = r0 + 8;
            float v00 = acc[mt][n8][0] + bb.x;
            float v01 = acc[mt][n8][1] + bb.y;
            float v10 = acc[mt][n8][2] + bb.x;
            float v11 = acc[mt][n8][3] + bb.y;

            if (MODE == 0) {
                __half* dst = shared_part ? OutHs : OutH;
                bool ok0 = shared_part ? (r0 < TOK) : true;
                bool ok1 = shared_part ? (r1 < TOK) : true;
                if (ok0) {
                    __half2 h = __floats2half2_rn(gelu_exact(v00),
                                                  gelu_exact(v01));
                    *reinterpret_cast<__half2*>(dst + (size_t)r0 * ND + col) = h;
                }
                if (ok1) {
                    __half2 h = __floats2half2_rn(gelu_exact(v10),
                                                  gelu_exact(v11));
                    *reinterpret_cast<__half2*>(dst + (size_t)r1 * ND + col) = h;
                }
            } else if (MODE == 1) {
                float w0 = g_w_of_row[r0], w1 = g_w_of_row[r1];
                float2 o0 = { v00 * w0, v01 * w0 };
                float2 o1 = { v10 * w1, v11 * w1 };
                *reinterpret_cast<float2*>(OutF + (size_t)r0 * ND + col) = o0;
                *reinterpret_cast<float2*>(OutF + (size_t)r1 * ND + col) = o1;
            } else { // MODE 3
                if (r0 < TOK) {
                    float o0 = v00, o1 = v01;
                    #pragma unroll
                    for (int k = 0; k < TOPK; k++) {
                        int rr = g_rows_of_tok[r0 * TOPK + k];
                        float2 e = *reinterpret_cast<const float2*>(
                            g_EO + (size_t)rr * DDIM + col);
                        o0 += e.x; o1 += e.y;
                    }
                    float2 o = { o0, o1 };
                    *reinterpret_cast<float2*>(OutF + (size_t)r0 * ND + col) = o;
                }
                if (r1 < TOK) {
                    float o0 = v10, o1 = v11;
                    #pragma unroll
                    for (int k = 0; k < TOPK; k++) {
                        int rr = g_rows_of_tok[r1 * TOPK + k];
                        float2 e = *reinterpret_cast<const float2*>(
                            g_EO + (size_t)rr * DDIM + col);
                        o0 += e.x; o1 += e.y;
                    }
                    float2 o = { o0, o1 };
                    *reinterpret_cast<float2*>(OutF + (size_t)r1 * ND + col) = o;
                }
            }
        }
    }
}

// ---------------------------------------------------------------------------
extern "C" void kernel_launch(void* const* d_in, const int* in_sizes, int n_in,
                              void* d_out, int out_size)
{
    const float* x      = (const float*)d_in[0];
    const float* gate_w = (const float*)d_in[1];
    const float* gate_b = (const float*)d_in[2];
    const float* w1     = (const float*)d_in[3];
    const float* b1     = (const float*)d_in[4];
    const float* w2     = (const float*)d_in[5];
    const float* b2     = (const float*)d_in[6];
    const float* ws1    = (const float*)d_in[7];
    const float* bs1    = (const float*)d_in[8];
    const float* ws2    = (const float*)d_in[9];
    const float* bs2    = (const float*)d_in[10];
    float* out = (float*)d_out;

    __half *xb, *w1b, *w2b, *ws1b, *ws2b, *Hb, *Hsb;
    float  *EOp;
    cudaGetSymbolAddress((void**)&xb,   g_xb);
    cudaGetSymbolAddress((void**)&w1b,  g_w1b);
    cudaGetSymbolAddress((void**)&w2b,  g_w2b);
    cudaGetSymbolAddress((void**)&ws1b, g_ws1b);
    cudaGetSymbolAddress((void**)&ws2b, g_ws2b);
    cudaGetSymbolAddress((void**)&Hb,   g_Hb);
    cudaGetSymbolAddress((void**)&Hsb,  g_Hsb);
    cudaGetSymbolAddress((void**)&EOp,  g_EO);

    cudaFuncSetAttribute(hgemm_kernel<0, DDIM, HDIM>,
                         cudaFuncAttributeMaxDynamicSharedMemorySize, DSM_BYTES);
    cudaFuncSetAttribute(hgemm_kernel<1, HDIM, DDIM>,
                         cudaFuncAttributeMaxDynamicSharedMemorySize, DSM_BYTES);
    cudaFuncSetAttribute(hgemm_kernel<3, HDIM, DDIM>,
                         cudaFuncAttributeMaxDynamicSharedMemorySize, DSM_BYTES);

    init_kernel<<<(MAXR + 255) / 256, 256>>>();
    gate_kernel<<<TOK, 128>>>(x, gate_w, gate_b);
    offsets_aux_kernel<<<1, 32>>>(out, out_size);
    scatter_kernel<<<(TOK * TOPK + 255) / 256, 256>>>();
    convert_w_kernel<<<(NC_TOT + 255) / 256, 256>>>(w1, w2, ws1, ws2);

    // merged layer1: expert tiles [0,MT) + shared tiles [MT, MT+TS_TILES)
    {
        dim3 grid(MT + TS_TILES, HDIM / BN);
        hgemm_kernel<0, DDIM, HDIM><<<grid, 128, DSM_BYTES>>>(
            xb, w1b, b1, ws1b, bs1, Hb, Hsb, nullptr);
    }
    // expert layer2
    {
        dim3 grid(MT, DDIM / BN);
        hgemm_kernel<1, HDIM, DDIM><<<grid, 128, DSM_BYTES>>>(
            Hb, w2b, b2, nullptr, nullptr, nullptr, nullptr, EOp);
    }
    // shared layer2 + combine
    {
        dim3 grid(TS_TILES, DDIM / BN);
        hgemm_kernel<3, HDIM, DDIM><<<grid, 128, DSM_BYTES>>>(
            Hsb, ws2b, bs2, nullptr, nullptr, nullptr, nullptr, out);
    }
}